// round 4
// baseline (speedup 1.0000x reference)
#include <cuda_runtime.h>
#include <cuda_bf16.h>
#include <math.h>

#define NO 64
#define NH 128
#define NB_MAX 600

// Scratch (allocation-free): per-frame hists R*3*T*nb = 1,440,000 floats + u.
__device__ float g_hists[1600000];
__device__ float g_u[4096];          // per-(rp,t) frame weights
__device__ float g_maes[32 * 3];
__device__ unsigned g_cnt;           // completion counter (reset by last block)

// ---------------------------------------------------------------------------
// Branchless pair visit: min-image distance -> bin -> predicated shared red.
// ---------------------------------------------------------------------------
__device__ __forceinline__ void do_pair(
    const float4 A, const float4 B,
    const float L0, const float L1, const float L2,
    const float b0, const float bN, const float inv_dx, const float kc,
    const int nbm1, const float* __restrict__ bins_s,
    const unsigned hbase, const int w)
{
    float dx = fabsf(A.x - B.x); dx = fminf(dx, L0 - dx);
    float dy = fabsf(A.y - B.y); dy = fminf(dy, L1 - dy);
    float dz = fabsf(A.z - B.z); dz = fminf(dz, L2 - dz);
    const float s = fmaf(dx, dx, fmaf(dy, dy, dz * dz));

    // d = sqrt(s) via rsqrt.approx + one Newton step (~1 ulp).
    // s == 0 (self pair) -> inf -> NaN -> both range predicates false.
    float y; asm("rsqrt.approx.f32 %0, %1;" : "=f"(y) : "f"(s));
    const float x = s * y;
    const float d = x * fmaf(-0.5f * x, y, 1.5f);

    int k = (int)fmaf(d, inv_dx, kc);
    k = min(max(k, 0), nbm1);
    const float lo = bins_s[k];
    const float hi = bins_s[k + 1];
    k += (int)((hi <= d) & (k < nbm1));       // exact searchsorted fixup
    k -= (int)((lo >  d) & (k > 0));          // (mutually exclusive, branchless)

    const int ok = (int)((d >= b0) & (d <= bN));
    const unsigned addr = hbase + ((unsigned)k << 2);
    asm volatile(
        "{\n\t.reg .pred p;\n\t"
        "setp.ne.s32 p, %0, 0;\n\t"
        "@p red.shared.add.u32 [%1], %2;\n\t}"
        :: "r"(ok), "r"(addr), "r"(w) : "memory");
}

// ---------------------------------------------------------------------------
// Per-(replica, pair-type, frame) histogram. blockIdx.x = (r*3+p)*T + t
// Self-contained: ballot-compacts idx lists, builds the histogram, and also
// computes this frame's weight u = sum_b h[b]/shell[b].
// ---------------------------------------------------------------------------
__global__ __launch_bounds__(256) void hist_kernel(
    const float* __restrict__ radii,   // (T, R, N, 3)
    const int*   __restrict__ ptypes,  // (N,)
    const float* __restrict__ lat,     // (3,)
    const float* __restrict__ bins,    // (nb+1,)
    int T, int R, int N, int nb)
{
    __shared__ int idxO_s[NO];
    __shared__ int idxH_s[NH];
    __shared__ float4 sO[NO];
    __shared__ float4 sH[NH];
    __shared__ float bins_s[NB_MAX + 1];
    __shared__ int hist[NB_MAX];
    __shared__ float red[256];
    __shared__ int cO[8], cH[8], oO[8], oH[8];
    __shared__ int totO_s, totH_s;

    const int bid = blockIdx.x;
    const int t  = bid % T;
    const int rp = bid / T;
    const int p  = rp % 3;
    const int r  = rp / 3;
    const int tid = threadIdx.x;
    const int wid = tid >> 5, lane = tid & 31;

    // ---- ballot-compaction of O/H index lists (N <= 256) ----
    const int ty = (tid < N) ? ptypes[tid] : -1;
    const unsigned mO = __ballot_sync(0xffffffffu, ty == 8);
    const unsigned mH = __ballot_sync(0xffffffffu, ty == 1);
    if (lane == 0) { cO[wid] = __popc(mO); cH[wid] = __popc(mH); }
    for (int i = tid; i <= nb; i += 256) bins_s[i] = bins[i];
    for (int i = tid; i < nb; i += 256) hist[i] = 0;
    __syncthreads();
    if (tid == 0) {
        int aO = 0, aH = 0;
        #pragma unroll
        for (int w = 0; w < 8; w++) {
            oO[w] = aO; aO += cO[w];
            oH[w] = aH; aH += cH[w];
        }
        totO_s = aO; totH_s = aH;
    }
    __syncthreads();
    const unsigned lt = (1u << lane) - 1u;
    if (ty == 8) { int pos = oO[wid] + __popc(mO & lt); if (pos < NO) idxO_s[pos] = tid; }
    if (ty == 1) { int pos = oH[wid] + __popc(mH & lt); if (pos < NH) idxH_s[pos] = tid; }
    for (int j = totO_s + tid; j < NO; j += 256) idxO_s[j] = 0;
    for (int j = totH_s + tid; j < NH; j += 256) idxH_s[j] = 0;
    __syncthreads();

    const float L0 = lat[0], L1 = lat[1], L2 = lat[2];

    // ---- gather + wrap: w = (x/L - floor(x/L)) * L ----
    const float* base = radii + ((size_t)t * R + r) * (size_t)N * 3;
    for (int i = tid; i < NO; i += 256) {
        const int g = idxO_s[i];
        float f0 = base[3 * g    ] / L0;
        float f1 = base[3 * g + 1] / L1;
        float f2 = base[3 * g + 2] / L2;
        sO[i] = make_float4((f0 - floorf(f0)) * L0, (f1 - floorf(f1)) * L1,
                            (f2 - floorf(f2)) * L2, 0.0f);
    }
    for (int i = tid; i < NH; i += 256) {
        const int g = idxH_s[i];
        float f0 = base[3 * g    ] / L0;
        float f1 = base[3 * g + 1] / L1;
        float f2 = base[3 * g + 2] / L2;
        sH[i] = make_float4((f0 - floorf(f0)) * L0, (f1 - floorf(f1)) * L1,
                            (f2 - floorf(f2)) * L2, 0.0f);
    }
    __syncthreads();

    const float b0 = bins_s[0], bN = bins_s[nb];
    const float inv_dx = (float)nb / (bN - b0);
    const float kc = -b0 * inv_dx;
    const int nbm1 = nb - 1;
    const unsigned hbase = (unsigned)__cvta_generic_to_shared(hist);

    // Symmetric types (OO, HH): each unordered pair once, weight 2
    // (weight 1 at the half-offset) -> counts identical to the full matrix.
    if (p < 2) {
        const float4* arr = (p == 0) ? sO : sH;
        const int n    = (p == 0) ? NO : NH;
        const int step = 256 / n;
        const int j    = tid & (n - 1);
        const int c0   = tid / n;
        const int half = n >> 1;
        const float4 B = arr[j];
        #pragma unroll 4
        for (int o = 1 + c0; o <= half; o += step) {
            const int i = (j + o) & (n - 1);
            const int w = (o == half) ? 1 : 2;
            do_pair(arr[i], B, L0, L1, L2, b0, bN, inv_dx, kc, nbm1,
                    bins_s, hbase, w);
        }
    } else {
        const int j  = tid & (NO - 1);
        const int c0 = tid >> 6;
        const float4 B = sO[j];
        #pragma unroll 4
        for (int i = c0; i < NH; i += 4) {
            do_pair(sH[i], B, L0, L1, L2, b0, bN, inv_dx, kc, nbm1,
                    bins_s, hbase, 1);
        }
    }
    __syncthreads();

    // ---- write hist + compute frame weight u = sum_b h[b]/shell[b] ----
    const float c43pi = (float)(4.0 / 3.0 * M_PI);
    float* gh = g_hists + ((size_t)rp * T + t) * nb;
    float acc = 0.0f;
    for (int i = tid; i < nb; i += 256) {
        const float h = (float)hist[i];
        gh[i] = h;
        const float lo = bins_s[i], hi = bins_s[i + 1];
        acc += h / (c43pi * (hi * hi * hi - lo * lo * lo));
    }
    red[tid] = acc;
    __syncthreads();
    #pragma unroll
    for (int s = 128; s > 0; s >>= 1) {
        if (tid < s) red[tid] += red[tid + s];
        __syncthreads();
    }
    if (tid == 0) g_u[rp * T + t] = red[0];
}

// ---------------------------------------------------------------------------
// Per-(replica, pair-type): rdf + MAE from precomputed per-frame weights.
// rdf[b] = (S/T) * sum_t h[t,b] * inv_shell[b] / u_t,
// S = (vol/(T*P)) * sum_t u_t. Last block also writes per-replica MAE max.
// ---------------------------------------------------------------------------
__global__ __launch_bounds__(256) void reduce_kernel(
    const float* __restrict__ bins,
    const float* __restrict__ lat,
    const float* __restrict__ gt_oo,
    const float* __restrict__ gt_hh,
    const float* __restrict__ gt_ho,
    float* __restrict__ out,
    int T, int nb, int R)
{
    __shared__ float invsh[NB_MAX];
    __shared__ float invU[128];
    __shared__ float red[256];
    __shared__ int sdone;

    const int rp = blockIdx.x;
    const int p = rp % 3;
    const int r = rp / 3;
    const int tid = threadIdx.x;

    const float c43pi = (float)(4.0 / 3.0 * M_PI);
    for (int b = tid; b < nb; b += 256) {
        const float lo = bins[b], hi = bins[b + 1];
        invsh[b] = 1.0f / (c43pi * (hi * hi * hi - lo * lo * lo));
    }
    if (tid < 128) invU[tid] = 0.0f;
    __syncthreads();
    if (tid < T) invU[tid] = g_u[rp * T + tid];
    __syncthreads();

    // S from sum_t u_t
    red[tid] = (tid < 128) ? invU[tid] : 0.0f;
    __syncthreads();
    #pragma unroll
    for (int s = 128; s > 0; s >>= 1) {
        if (tid < s) red[tid] += red[tid + s];
        __syncthreads();
    }
    const float sumU = red[0];
    __syncthreads();
    if (tid < T) invU[tid] = 1.0f / invU[tid];
    __syncthreads();

    const float vol = lat[0] * lat[1] * lat[2];
    const int P = (p == 0) ? NO * NO : (p == 1) ? NH * NH : NH * NO;
    const float SinvT = vol / ((float)T * (float)P) * sumU / (float)T;
    const float* gt = (p == 0) ? gt_oo : (p == 1) ? gt_hh : gt_ho;
    const float* H = g_hists + (size_t)rp * T * nb;

    float* ro = out + ((size_t)r * 3 + p) * nb;
    float myabs = 0.0f;
    for (int b = tid; b < nb; b += 256) {
        float num = 0.0f;
        #pragma unroll 4
        for (int t = 0; t < T; t++)
            num = fmaf(H[(size_t)t * nb + b], invU[t], num);
        const float rdf = SinvT * num * invsh[b];
        ro[b] = rdf;
        myabs += fabsf(rdf - gt[b]);
    }
    red[tid] = myabs;
    __syncthreads();
    #pragma unroll
    for (int s = 128; s > 0; s >>= 1) {
        if (tid < s) red[tid] += red[tid + s];
        __syncthreads();
    }
    if (tid == 0) {
        g_maes[rp] = 6.0f * red[0] / (float)nb;   // XLIM * mean
        __threadfence();
        unsigned old = atomicAdd(&g_cnt, 1u);
        sdone = (int)(old == (unsigned)(3 * R - 1));
    }
    __syncthreads();
    if (sdone) {
        __threadfence();
        if (tid == 0) g_cnt = 0;                  // reset for next graph replay
        if (tid < R) {
            volatile float* gm = g_maes;
            float m = gm[tid * 3];
            m = fmaxf(m, gm[tid * 3 + 1]);
            m = fmaxf(m, gm[tid * 3 + 2]);
            out[(size_t)R * 3 * nb + tid] = m;
        }
    }
}

// ---------------------------------------------------------------------------
extern "C" void kernel_launch(void* const* d_in, const int* in_sizes, int n_in,
                              void* d_out, int out_size) {
    const float* radii  = (const float*)d_in[0];   // (T,R,N,3)
    const int*   ptypes = (const int*)d_in[1];     // (N,)
    const float* lat    = (const float*)d_in[2];   // (3,)
    const float* bins   = (const float*)d_in[3];   // (nb+1,)
    const float* gt_oo  = (const float*)d_in[4];
    const float* gt_hh  = (const float*)d_in[5];
    const float* gt_ho  = (const float*)d_in[6];
    float* out = (float*)d_out;

    const int nb = in_sizes[3] - 1;                 // 600
    const int N  = in_sizes[1];                     // 192
    const int R  = out_size / (3 * nb + 1);         // 8
    const int T  = in_sizes[0] / (R * N * 3);       // 100

    hist_kernel<<<R * 3 * T, 256>>>(radii, ptypes, lat, bins, T, R, N, nb);
    reduce_kernel<<<R * 3, 256>>>(bins, lat, gt_oo, gt_hh, gt_ho, out, T, nb, R);
}

// round 5
// speedup vs baseline: 1.4302x; 1.4302x over previous
#include <cuda_runtime.h>
#include <cuda_bf16.h>
#include <math.h>

#define NO 64
#define NH 128
#define NB_MAX 600

// Scratch (allocation-free): per-frame hists R*3*T*nb = 1,440,000 floats.
__device__ float g_hists[1600000];
__device__ float g_maes[32 * 3];
__device__ float g_inv_shell[NB_MAX];
__device__ int g_idxO[NO];
__device__ int g_idxH[NH];
__device__ unsigned g_cnt;           // completion counter (reset by last block)

// ---------------------------------------------------------------------------
// init: ballot-compaction of O/H index lists + reciprocal shell volumes.
// ---------------------------------------------------------------------------
__global__ __launch_bounds__(256) void init_kernel(
    const int* __restrict__ ptypes, const float* __restrict__ bins,
    int N, int nb)
{
    __shared__ int cntO[8], cntH[8], offO[8], offH[8];
    __shared__ int totO_s, totH_s;
    const int tid = threadIdx.x;
    const int wid = tid >> 5, lane = tid & 31;

    const int ty = (tid < N) ? ptypes[tid] : -1;
    const unsigned mO = __ballot_sync(0xffffffffu, ty == 8);
    const unsigned mH = __ballot_sync(0xffffffffu, ty == 1);
    if (lane == 0) { cntO[wid] = __popc(mO); cntH[wid] = __popc(mH); }
    __syncthreads();
    if (tid == 0) {
        int aO = 0, aH = 0;
        #pragma unroll
        for (int w = 0; w < 8; w++) {
            offO[w] = aO; aO += cntO[w];
            offH[w] = aH; aH += cntH[w];
        }
        totO_s = aO; totH_s = aH;
    }
    __syncthreads();
    const unsigned lt = (1u << lane) - 1u;
    if (ty == 8) { int pos = offO[wid] + __popc(mO & lt); if (pos < NO) g_idxO[pos] = tid; }
    if (ty == 1) { int pos = offH[wid] + __popc(mH & lt); if (pos < NH) g_idxH[pos] = tid; }
    for (int j = totO_s + tid; j < NO; j += 256) g_idxO[j] = 0;
    for (int j = totH_s + tid; j < NH; j += 256) g_idxH[j] = 0;

    const float c = (float)(4.0 / 3.0 * M_PI);
    for (int b = tid; b < nb; b += 256) {
        const float lo = bins[b], hi = bins[b + 1];
        g_inv_shell[b] = 1.0f / (c * (hi * hi * hi - lo * lo * lo));
    }
}

// ---------------------------------------------------------------------------
// Branchless pair visit: min-image distance -> bin -> predicated shared red.
// ---------------------------------------------------------------------------
__device__ __forceinline__ void do_pair(
    const float4 A, const float4 B,
    const float L0, const float L1, const float L2,
    const float b0, const float bN, const float inv_dx, const float kc,
    const int nbm1, const float* __restrict__ bins_s,
    const unsigned hbase, const int w)
{
    float dx = fabsf(A.x - B.x); dx = fminf(dx, L0 - dx);
    float dy = fabsf(A.y - B.y); dy = fminf(dy, L1 - dy);
    float dz = fabsf(A.z - B.z); dz = fminf(dz, L2 - dz);
    const float s = fmaf(dx, dx, fmaf(dy, dy, dz * dz));

    // d = sqrt(s) via rsqrt.approx + one Newton step (~1 ulp).
    // s == 0 (self pair) -> inf -> NaN -> both range predicates false.
    float y; asm("rsqrt.approx.f32 %0, %1;" : "=f"(y) : "f"(s));
    const float x = s * y;
    const float d = x * fmaf(-0.5f * x, y, 1.5f);

    int k = (int)fmaf(d, inv_dx, kc);
    k = min(max(k, 0), nbm1);
    const float lo = bins_s[k];
    const float hi = bins_s[k + 1];
    k += (int)((hi <= d) & (k < nbm1));       // exact searchsorted fixup
    k -= (int)((lo >  d) & (k > 0));          // (mutually exclusive, branchless)

    const int ok = (int)((d >= b0) & (d <= bN));
    const unsigned addr = hbase + ((unsigned)k << 2);
    asm volatile(
        "{\n\t.reg .pred p;\n\t"
        "setp.ne.s32 p, %0, 0;\n\t"
        "@p red.shared.add.u32 [%1], %2;\n\t}"
        :: "r"(ok), "r"(addr), "r"(w) : "memory");
}

// ---------------------------------------------------------------------------
// Per-(replica, pair-type, frame) histogram. blockIdx.x = (r*3+p)*T + t
// ---------------------------------------------------------------------------
__global__ __launch_bounds__(256) void hist_kernel(
    const float* __restrict__ radii,   // (T, R, N, 3)
    const float* __restrict__ lat,     // (3,)
    const float* __restrict__ bins,    // (nb+1,)
    int T, int R, int N, int nb)
{
    __shared__ float4 sO[NO];
    __shared__ float4 sH[NH];
    __shared__ float bins_s[NB_MAX + 1];
    __shared__ int hist[NB_MAX];

    const int bid = blockIdx.x;
    const int t  = bid % T;
    const int rp = bid / T;
    const int p  = rp % 3;
    const int r  = rp / 3;
    const int tid = threadIdx.x;

    const float L0 = lat[0], L1 = lat[1], L2 = lat[2];

    const float* base = radii + ((size_t)t * R + r) * (size_t)N * 3;
    for (int i = tid; i < NO; i += 256) {
        const int g = g_idxO[i];
        float f0 = base[3 * g    ] / L0;
        float f1 = base[3 * g + 1] / L1;
        float f2 = base[3 * g + 2] / L2;
        sO[i] = make_float4((f0 - floorf(f0)) * L0, (f1 - floorf(f1)) * L1,
                            (f2 - floorf(f2)) * L2, 0.0f);
    }
    for (int i = tid; i < NH; i += 256) {
        const int g = g_idxH[i];
        float f0 = base[3 * g    ] / L0;
        float f1 = base[3 * g + 1] / L1;
        float f2 = base[3 * g + 2] / L2;
        sH[i] = make_float4((f0 - floorf(f0)) * L0, (f1 - floorf(f1)) * L1,
                            (f2 - floorf(f2)) * L2, 0.0f);
    }
    for (int i = tid; i <= nb; i += 256) bins_s[i] = bins[i];
    for (int i = tid; i < nb; i += 256) hist[i] = 0;
    __syncthreads();

    const float b0 = bins_s[0], bN = bins_s[nb];
    const float inv_dx = (float)nb / (bN - b0);
    const float kc = -b0 * inv_dx;
    const int nbm1 = nb - 1;
    const unsigned hbase = (unsigned)__cvta_generic_to_shared(hist);

    // Symmetric types (OO, HH): each unordered pair once, weight 2
    // (weight 1 at the half-offset) -> counts identical to the full matrix.
    if (p < 2) {
        const float4* arr = (p == 0) ? sO : sH;
        const int n    = (p == 0) ? NO : NH;
        const int step = 256 / n;
        const int j    = tid & (n - 1);
        const int c0   = tid / n;
        const int half = n >> 1;
        const float4 B = arr[j];
        #pragma unroll 4
        for (int o = 1 + c0; o <= half; o += step) {
            const int i = (j + o) & (n - 1);
            const int w = (o == half) ? 1 : 2;
            do_pair(arr[i], B, L0, L1, L2, b0, bN, inv_dx, kc, nbm1,
                    bins_s, hbase, w);
        }
    } else {
        const int j  = tid & (NO - 1);
        const int c0 = tid >> 6;
        const float4 B = sO[j];
        #pragma unroll 4
        for (int i = c0; i < NH; i += 4) {
            do_pair(sH[i], B, L0, L1, L2, b0, bN, inv_dx, kc, nbm1,
                    bins_s, hbase, 1);
        }
    }
    __syncthreads();

    float* gh = g_hists + ((size_t)rp * T + t) * nb;
    for (int i = tid; i < nb; i += 256) gh[i] = (float)hist[i];
}

// ---------------------------------------------------------------------------
// Per-(replica, pair-type): u_t (warp-per-frame, coalesced), rdf + MAE.
// rdf[b] = (S/T) * sum_t h[t,b] * inv_shell[b] / u_t,
// u_t = sum_b h[t,b]*inv_shell[b],  S = (vol/(T*P)) * sum_t u_t
// ---------------------------------------------------------------------------
__global__ __launch_bounds__(256) void reduce_kernel(
    const float* __restrict__ lat,
    const float* __restrict__ gt_oo,
    const float* __restrict__ gt_hh,
    const float* __restrict__ gt_ho,
    float* __restrict__ out,
    int T, int nb, int R)
{
    __shared__ float invsh[NB_MAX];
    __shared__ float invU[128];
    __shared__ float red[256];
    __shared__ int sdone;

    const int rp = blockIdx.x;
    const int p = rp % 3;
    const int r = rp / 3;
    const int tid = threadIdx.x;
    const int wid = tid >> 5, lane = tid & 31;

    for (int b = tid; b < nb; b += 256) invsh[b] = g_inv_shell[b];
    if (tid < 128) invU[tid] = 0.0f;
    __syncthreads();

    const float* H = g_hists + (size_t)rp * T * nb;

    // ---- u_t: one warp per frame, lanes stride bins (coalesced) ----
    for (int t = wid; t < T; t += 8) {
        const float* row = H + (size_t)t * nb;
        float acc = 0.0f;
        for (int b = lane; b < nb; b += 32)
            acc = fmaf(row[b], invsh[b], acc);
        #pragma unroll
        for (int o = 16; o > 0; o >>= 1)
            acc += __shfl_xor_sync(0xffffffffu, acc, o);
        if (lane == 0) invU[t] = acc;
    }
    __syncthreads();

    // ---- sum_t u_t -> S ; then invert u ----
    red[tid] = (tid < 128) ? invU[tid] : 0.0f;
    __syncthreads();
    #pragma unroll
    for (int s = 128; s > 0; s >>= 1) {
        if (tid < s) red[tid] += red[tid + s];
        __syncthreads();
    }
    const float sumU = red[0];
    __syncthreads();
    if (tid < T) invU[tid] = 1.0f / invU[tid];
    __syncthreads();

    const float vol = lat[0] * lat[1] * lat[2];
    const int P = (p == 0) ? NO * NO : (p == 1) ? NH * NH : NH * NO;
    const float SinvT = vol / ((float)T * (float)P) * sumU / (float)T;
    const float* gt = (p == 0) ? gt_oo : (p == 1) ? gt_hh : gt_ho;

    // ---- rdf pass: each thread owns bins tid, tid+256, tid+512 in ONE
    //      t-loop -> 3 independent load streams, coalesced across the warp.
    const int b0i = tid;
    const int b1i = tid + 256;
    const int b2i = tid + 512;
    const int v1 = (b1i < nb), v2 = (b2i < nb);
    const int a1 = v1 ? b1i : 0;
    const int a2 = v2 ? b2i : 0;
    float n0 = 0.0f, n1 = 0.0f, n2 = 0.0f;
    #pragma unroll 4
    for (int t = 0; t < T; t++) {
        const float* row = H + (size_t)t * nb;
        const float w = invU[t];
        n0 = fmaf(row[b0i], w, n0);
        n1 = fmaf(row[a1],  w, n1);
        n2 = fmaf(row[a2],  w, n2);
    }

    float* ro = out + ((size_t)r * 3 + p) * nb;
    float myabs = 0.0f;
    {
        const float rdf = SinvT * n0 * invsh[b0i];
        if (b0i < nb) { ro[b0i] = rdf; myabs += fabsf(rdf - gt[b0i]); }
    }
    if (v1) {
        const float rdf = SinvT * n1 * invsh[b1i];
        ro[b1i] = rdf; myabs += fabsf(rdf - gt[b1i]);
    }
    if (v2) {
        const float rdf = SinvT * n2 * invsh[b2i];
        ro[b2i] = rdf; myabs += fabsf(rdf - gt[b2i]);
    }
    red[tid] = myabs;
    __syncthreads();
    #pragma unroll
    for (int s = 128; s > 0; s >>= 1) {
        if (tid < s) red[tid] += red[tid + s];
        __syncthreads();
    }
    if (tid == 0) {
        g_maes[rp] = 6.0f * red[0] / (float)nb;   // XLIM * mean
        __threadfence();
        unsigned old = atomicAdd(&g_cnt, 1u);
        sdone = (int)(old == (unsigned)(3 * R - 1));
    }
    __syncthreads();
    if (sdone) {
        __threadfence();
        if (tid == 0) g_cnt = 0;                  // reset for next graph replay
        if (tid < R) {
            volatile float* gm = g_maes;
            float m = gm[tid * 3];
            m = fmaxf(m, gm[tid * 3 + 1]);
            m = fmaxf(m, gm[tid * 3 + 2]);
            out[(size_t)R * 3 * nb + tid] = m;
        }
    }
}

// ---------------------------------------------------------------------------
extern "C" void kernel_launch(void* const* d_in, const int* in_sizes, int n_in,
                              void* d_out, int out_size) {
    const float* radii  = (const float*)d_in[0];   // (T,R,N,3)
    const int*   ptypes = (const int*)d_in[1];     // (N,)
    const float* lat    = (const float*)d_in[2];   // (3,)
    const float* bins   = (const float*)d_in[3];   // (nb+1,)
    const float* gt_oo  = (const float*)d_in[4];
    const float* gt_hh  = (const float*)d_in[5];
    const float* gt_ho  = (const float*)d_in[6];
    float* out = (float*)d_out;

    const int nb = in_sizes[3] - 1;                 // 600
    const int N  = in_sizes[1];                     // 192
    const int R  = out_size / (3 * nb + 1);         // 8
    const int T  = in_sizes[0] / (R * N * 3);       // 100

    init_kernel<<<1, 256>>>(ptypes, bins, N, nb);
    hist_kernel<<<R * 3 * T, 256>>>(radii, lat, bins, T, R, N, nb);
    reduce_kernel<<<R * 3, 256>>>(lat, gt_oo, gt_hh, gt_ho, out, T, nb, R);
}

// round 6
// speedup vs baseline: 1.4802x; 1.0350x over previous
#include <cuda_runtime.h>
#include <cuda_bf16.h>
#include <math.h>

#define NO 64
#define NH 128
#define NB_MAX 600

// Scratch (allocation-free): per-frame hists R*3*T*nb = 1,440,000 floats.
__device__ float g_hists[1600000];
__device__ float g_maes[32 * 3];
__device__ unsigned g_cnt;           // completion counter (reset by last block)

// ---------------------------------------------------------------------------
// Branchless pair visit: min-image distance -> bin -> predicated shared red.
// ---------------------------------------------------------------------------
__device__ __forceinline__ void do_pair(
    const float4 A, const float4 B,
    const float L0, const float L1, const float L2,
    const float b0, const float bN, const float inv_dx, const float kc,
    const int nbm1, const float* __restrict__ bins_s,
    const unsigned hbase, const int w)
{
    float dx = fabsf(A.x - B.x); dx = fminf(dx, L0 - dx);
    float dy = fabsf(A.y - B.y); dy = fminf(dy, L1 - dy);
    float dz = fabsf(A.z - B.z); dz = fminf(dz, L2 - dz);
    const float s = fmaf(dx, dx, fmaf(dy, dy, dz * dz));

    // d = sqrt(s) via rsqrt.approx + one Newton step (~1 ulp).
    // s == 0 (self pair) -> inf -> NaN -> both range predicates false.
    float y; asm("rsqrt.approx.f32 %0, %1;" : "=f"(y) : "f"(s));
    const float x = s * y;
    const float d = x * fmaf(-0.5f * x, y, 1.5f);

    int k = (int)fmaf(d, inv_dx, kc);
    k = min(max(k, 0), nbm1);
    const float lo = bins_s[k];
    const float hi = bins_s[k + 1];
    k += (int)((hi <= d) & (k < nbm1));       // exact searchsorted fixup
    k -= (int)((lo >  d) & (k > 0));          // (mutually exclusive, branchless)

    const int ok = (int)((d >= b0) & (d <= bN));
    const unsigned addr = hbase + ((unsigned)k << 2);
    asm volatile(
        "{\n\t.reg .pred p;\n\t"
        "setp.ne.s32 p, %0, 0;\n\t"
        "@p red.shared.add.u32 [%1], %2;\n\t}"
        :: "r"(ok), "r"(addr), "r"(w) : "memory");
}

// ---------------------------------------------------------------------------
// Per-(replica, pair-type, frame) histogram. blockIdx.x = (r*3+p)*T + t
// Self-contained ballot-compaction of idx lists (no serial init launch).
// ---------------------------------------------------------------------------
__global__ __launch_bounds__(256) void hist_kernel(
    const float* __restrict__ radii,   // (T, R, N, 3)
    const int*   __restrict__ ptypes,  // (N,)
    const float* __restrict__ lat,     // (3,)
    const float* __restrict__ bins,    // (nb+1,)
    int T, int R, int N, int nb)
{
    __shared__ int idxO_s[NO];
    __shared__ int idxH_s[NH];
    __shared__ float4 sO[NO];
    __shared__ float4 sH[NH];
    __shared__ float bins_s[NB_MAX + 1];
    __shared__ int hist[NB_MAX];
    __shared__ int cO[8], cH[8], oO[8], oH[8];
    __shared__ int totO_s, totH_s;

    const int bid = blockIdx.x;
    const int t  = bid % T;
    const int rp = bid / T;
    const int p  = rp % 3;
    const int r  = rp / 3;
    const int tid = threadIdx.x;
    const int wid = tid >> 5, lane = tid & 31;

    // ---- ballot-compaction of O/H index lists (N <= 256) ----
    const int ty = (tid < N) ? ptypes[tid] : -1;
    const unsigned mO = __ballot_sync(0xffffffffu, ty == 8);
    const unsigned mH = __ballot_sync(0xffffffffu, ty == 1);
    if (lane == 0) { cO[wid] = __popc(mO); cH[wid] = __popc(mH); }
    // overlap: bins + hist init while warp counts settle
    for (int i = tid; i <= nb; i += 256) bins_s[i] = bins[i];
    for (int i = tid; i < nb; i += 256) hist[i] = 0;
    __syncthreads();
    if (tid == 0) {
        int aO = 0, aH = 0;
        #pragma unroll
        for (int w = 0; w < 8; w++) {
            oO[w] = aO; aO += cO[w];
            oH[w] = aH; aH += cH[w];
        }
        totO_s = aO; totH_s = aH;
    }
    __syncthreads();
    const unsigned lt = (1u << lane) - 1u;
    if (ty == 8) { int pos = oO[wid] + __popc(mO & lt); if (pos < NO) idxO_s[pos] = tid; }
    if (ty == 1) { int pos = oH[wid] + __popc(mH & lt); if (pos < NH) idxH_s[pos] = tid; }
    for (int j = totO_s + tid; j < NO; j += 256) idxO_s[j] = 0;
    for (int j = totH_s + tid; j < NH; j += 256) idxH_s[j] = 0;
    __syncthreads();

    const float L0 = lat[0], L1 = lat[1], L2 = lat[2];

    // ---- gather + wrap: w = (x/L - floor(x/L)) * L ----
    const float* base = radii + ((size_t)t * R + r) * (size_t)N * 3;
    for (int i = tid; i < NO; i += 256) {
        const int g = idxO_s[i];
        float f0 = base[3 * g    ] / L0;
        float f1 = base[3 * g + 1] / L1;
        float f2 = base[3 * g + 2] / L2;
        sO[i] = make_float4((f0 - floorf(f0)) * L0, (f1 - floorf(f1)) * L1,
                            (f2 - floorf(f2)) * L2, 0.0f);
    }
    for (int i = tid; i < NH; i += 256) {
        const int g = idxH_s[i];
        float f0 = base[3 * g    ] / L0;
        float f1 = base[3 * g + 1] / L1;
        float f2 = base[3 * g + 2] / L2;
        sH[i] = make_float4((f0 - floorf(f0)) * L0, (f1 - floorf(f1)) * L1,
                            (f2 - floorf(f2)) * L2, 0.0f);
    }
    __syncthreads();

    const float b0 = bins_s[0], bN = bins_s[nb];
    const float inv_dx = (float)nb / (bN - b0);
    const float kc = -b0 * inv_dx;
    const int nbm1 = nb - 1;
    const unsigned hbase = (unsigned)__cvta_generic_to_shared(hist);

    // Symmetric types (OO, HH): each unordered pair once, weight 2
    // (weight 1 at the half-offset) -> counts identical to the full matrix.
    if (p < 2) {
        const float4* arr = (p == 0) ? sO : sH;
        const int n    = (p == 0) ? NO : NH;
        const int step = 256 / n;
        const int j    = tid & (n - 1);
        const int c0   = tid / n;
        const int half = n >> 1;
        const float4 B = arr[j];
        #pragma unroll 4
        for (int o = 1 + c0; o <= half; o += step) {
            const int i = (j + o) & (n - 1);
            const int w = (o == half) ? 1 : 2;
            do_pair(arr[i], B, L0, L1, L2, b0, bN, inv_dx, kc, nbm1,
                    bins_s, hbase, w);
        }
    } else {
        const int j  = tid & (NO - 1);
        const int c0 = tid >> 6;
        const float4 B = sO[j];
        #pragma unroll 4
        for (int i = c0; i < NH; i += 4) {
            do_pair(sH[i], B, L0, L1, L2, b0, bN, inv_dx, kc, nbm1,
                    bins_s, hbase, 1);
        }
    }
    __syncthreads();

    float* gh = g_hists + ((size_t)rp * T + t) * nb;
    for (int i = tid; i < nb; i += 256) gh[i] = (float)hist[i];
}

// ---------------------------------------------------------------------------
// Per-(replica, pair-type): u_t (warp-per-frame, coalesced), rdf + MAE.
// rdf[b] = (S/T) * sum_t h[t,b] * inv_shell[b] / u_t,
// u_t = sum_b h[t,b]*inv_shell[b],  S = (vol/(T*P)) * sum_t u_t
// ---------------------------------------------------------------------------
__global__ __launch_bounds__(256) void reduce_kernel(
    const float* __restrict__ bins,
    const float* __restrict__ lat,
    const float* __restrict__ gt_oo,
    const float* __restrict__ gt_hh,
    const float* __restrict__ gt_ho,
    float* __restrict__ out,
    int T, int nb, int R)
{
    __shared__ float invsh[NB_MAX];
    __shared__ float invU[128];
    __shared__ float red[256];
    __shared__ int sdone;

    const int rp = blockIdx.x;
    const int p = rp % 3;
    const int r = rp / 3;
    const int tid = threadIdx.x;
    const int wid = tid >> 5, lane = tid & 31;

    const float c43pi = (float)(4.0 / 3.0 * M_PI);
    for (int b = tid; b < nb; b += 256) {
        const float lo = bins[b], hi = bins[b + 1];
        invsh[b] = 1.0f / (c43pi * (hi * hi * hi - lo * lo * lo));
    }
    if (tid < 128) invU[tid] = 0.0f;
    __syncthreads();

    const float* H = g_hists + (size_t)rp * T * nb;

    // ---- u_t: one warp per frame, lanes stride bins (coalesced) ----
    for (int t = wid; t < T; t += 8) {
        const float* row = H + (size_t)t * nb;
        float acc = 0.0f;
        for (int b = lane; b < nb; b += 32)
            acc = fmaf(row[b], invsh[b], acc);
        #pragma unroll
        for (int o = 16; o > 0; o >>= 1)
            acc += __shfl_xor_sync(0xffffffffu, acc, o);
        if (lane == 0) invU[t] = acc;
    }
    __syncthreads();

    // ---- sum_t u_t -> S ; then invert u ----
    red[tid] = (tid < 128) ? invU[tid] : 0.0f;
    __syncthreads();
    #pragma unroll
    for (int s = 128; s > 0; s >>= 1) {
        if (tid < s) red[tid] += red[tid + s];
        __syncthreads();
    }
    const float sumU = red[0];
    __syncthreads();
    if (tid < T) invU[tid] = 1.0f / invU[tid];
    __syncthreads();

    const float vol = lat[0] * lat[1] * lat[2];
    const int P = (p == 0) ? NO * NO : (p == 1) ? NH * NH : NH * NO;
    const float SinvT = vol / ((float)T * (float)P) * sumU / (float)T;
    const float* gt = (p == 0) ? gt_oo : (p == 1) ? gt_hh : gt_ho;

    // ---- rdf pass: each thread owns bins tid, tid+256, tid+512 in ONE
    //      t-loop -> 3 independent load streams, coalesced across the warp.
    const int b0i = tid;
    const int b1i = tid + 256;
    const int b2i = tid + 512;
    const int v1 = (b1i < nb), v2 = (b2i < nb);
    const int a1 = v1 ? b1i : 0;
    const int a2 = v2 ? b2i : 0;
    float n0 = 0.0f, n1 = 0.0f, n2 = 0.0f;
    #pragma unroll 4
    for (int t = 0; t < T; t++) {
        const float* row = H + (size_t)t * nb;
        const float w = invU[t];
        n0 = fmaf(row[b0i], w, n0);
        n1 = fmaf(row[a1],  w, n1);
        n2 = fmaf(row[a2],  w, n2);
    }

    float* ro = out + ((size_t)r * 3 + p) * nb;
    float myabs = 0.0f;
    {
        const float rdf = SinvT * n0 * invsh[b0i];
        if (b0i < nb) { ro[b0i] = rdf; myabs += fabsf(rdf - gt[b0i]); }
    }
    if (v1) {
        const float rdf = SinvT * n1 * invsh[b1i];
        ro[b1i] = rdf; myabs += fabsf(rdf - gt[b1i]);
    }
    if (v2) {
        const float rdf = SinvT * n2 * invsh[b2i];
        ro[b2i] = rdf; myabs += fabsf(rdf - gt[b2i]);
    }
    red[tid] = myabs;
    __syncthreads();
    #pragma unroll
    for (int s = 128; s > 0; s >>= 1) {
        if (tid < s) red[tid] += red[tid + s];
        __syncthreads();
    }
    if (tid == 0) {
        g_maes[rp] = 6.0f * red[0] / (float)nb;   // XLIM * mean
        __threadfence();
        unsigned old = atomicAdd(&g_cnt, 1u);
        sdone = (int)(old == (unsigned)(3 * R - 1));
    }
    __syncthreads();
    if (sdone) {
        __threadfence();
        if (tid == 0) g_cnt = 0;                  // reset for next graph replay
        if (tid < R) {
            volatile float* gm = g_maes;
            float m = gm[tid * 3];
            m = fmaxf(m, gm[tid * 3 + 1]);
            m = fmaxf(m, gm[tid * 3 + 2]);
            out[(size_t)R * 3 * nb + tid] = m;
        }
    }
}

// ---------------------------------------------------------------------------
extern "C" void kernel_launch(void* const* d_in, const int* in_sizes, int n_in,
                              void* d_out, int out_size) {
    const float* radii  = (const float*)d_in[0];   // (T,R,N,3)
    const int*   ptypes = (const int*)d_in[1];     // (N,)
    const float* lat    = (const float*)d_in[2];   // (3,)
    const float* bins   = (const float*)d_in[3];   // (nb+1,)
    const float* gt_oo  = (const float*)d_in[4];
    const float* gt_hh  = (const float*)d_in[5];
    const float* gt_ho  = (const float*)d_in[6];
    float* out = (float*)d_out;

    const int nb = in_sizes[3] - 1;                 // 600
    const int N  = in_sizes[1];                     // 192
    const int R  = out_size / (3 * nb + 1);         // 8
    const int T  = in_sizes[0] / (R * N * 3);       // 100

    hist_kernel<<<R * 3 * T, 256>>>(radii, ptypes, lat, bins, T, R, N, nb);
    reduce_kernel<<<R * 3, 256>>>(bins, lat, gt_oo, gt_hh, gt_ho, out, T, nb, R);
}

// round 7
// speedup vs baseline: 1.7094x; 1.1548x over previous
#include <cuda_runtime.h>
#include <cuda_bf16.h>
#include <math.h>

#define NO 64
#define NH 128
#define NB_MAX 600
#define NCH 6            // bin chunks for the rdf kernel

// Scratch (allocation-free): per-frame hists R*3*T*nb = 1,440,000 floats.
__device__ float g_hists[1600000];
__device__ float g_u[4096];           // per-(rp,t) frame weights
__device__ float g_mae_part[32 * NCH];
__device__ unsigned g_cnt;            // completion counter (reset by last block)

// ---------------------------------------------------------------------------
// Branchless pair visit: min-image distance -> bin -> predicated shared red.
// ---------------------------------------------------------------------------
__device__ __forceinline__ void do_pair(
    const float4 A, const float4 B,
    const float L0, const float L1, const float L2,
    const float b0, const float bN, const float inv_dx, const float kc,
    const int nbm1, const float* __restrict__ bins_s,
    const unsigned hbase, const int w)
{
    float dx = fabsf(A.x - B.x); dx = fminf(dx, L0 - dx);
    float dy = fabsf(A.y - B.y); dy = fminf(dy, L1 - dy);
    float dz = fabsf(A.z - B.z); dz = fminf(dz, L2 - dz);
    const float s = fmaf(dx, dx, fmaf(dy, dy, dz * dz));

    // d = sqrt(s) via rsqrt.approx + one Newton step (~1 ulp).
    // s == 0 (self pair) -> inf -> NaN -> both range predicates false.
    float y; asm("rsqrt.approx.f32 %0, %1;" : "=f"(y) : "f"(s));
    const float x = s * y;
    const float d = x * fmaf(-0.5f * x, y, 1.5f);

    int k = (int)fmaf(d, inv_dx, kc);
    k = min(max(k, 0), nbm1);
    const float lo = bins_s[k];
    const float hi = bins_s[k + 1];
    k += (int)((hi <= d) & (k < nbm1));       // exact searchsorted fixup
    k -= (int)((lo >  d) & (k > 0));          // (mutually exclusive, branchless)

    const int ok = (int)((d >= b0) & (d <= bN));
    const unsigned addr = hbase + ((unsigned)k << 2);
    asm volatile(
        "{\n\t.reg .pred p;\n\t"
        "setp.ne.s32 p, %0, 0;\n\t"
        "@p red.shared.add.u32 [%1], %2;\n\t}"
        :: "r"(ok), "r"(addr), "r"(w) : "memory");
}

// ---------------------------------------------------------------------------
// Per-(replica, pair-type, frame) histogram + frame weight u.
// blockIdx.x = (r*3+p)*T + t. Self-contained ballot-compaction of idx lists.
// ---------------------------------------------------------------------------
__global__ __launch_bounds__(256) void hist_kernel(
    const float* __restrict__ radii,   // (T, R, N, 3)
    const int*   __restrict__ ptypes,  // (N,)
    const float* __restrict__ lat,     // (3,)
    const float* __restrict__ bins,    // (nb+1,)
    int T, int R, int N, int nb)
{
    __shared__ int idxO_s[NO];
    __shared__ int idxH_s[NH];
    __shared__ float4 sO[NO];
    __shared__ float4 sH[NH];
    __shared__ float bins_s[NB_MAX + 1];
    __shared__ int hist[NB_MAX];
    __shared__ int cO[8], cH[8], oO[8], oH[8];
    __shared__ int totO_s, totH_s;

    const int bid = blockIdx.x;
    const int t  = bid % T;
    const int rp = bid / T;
    const int p  = rp % 3;
    const int r  = rp / 3;
    const int tid = threadIdx.x;
    const int wid = tid >> 5, lane = tid & 31;

    // ---- ballot-compaction of O/H index lists (N <= 256) ----
    const int ty = (tid < N) ? ptypes[tid] : -1;
    const unsigned mO = __ballot_sync(0xffffffffu, ty == 8);
    const unsigned mH = __ballot_sync(0xffffffffu, ty == 1);
    if (lane == 0) { cO[wid] = __popc(mO); cH[wid] = __popc(mH); }
    for (int i = tid; i <= nb; i += 256) bins_s[i] = bins[i];
    for (int i = tid; i < nb; i += 256) hist[i] = 0;
    __syncthreads();
    if (tid == 0) {
        int aO = 0, aH = 0;
        #pragma unroll
        for (int w = 0; w < 8; w++) {
            oO[w] = aO; aO += cO[w];
            oH[w] = aH; aH += cH[w];
        }
        totO_s = aO; totH_s = aH;
    }
    __syncthreads();
    const unsigned lt = (1u << lane) - 1u;
    if (ty == 8) { int pos = oO[wid] + __popc(mO & lt); if (pos < NO) idxO_s[pos] = tid; }
    if (ty == 1) { int pos = oH[wid] + __popc(mH & lt); if (pos < NH) idxH_s[pos] = tid; }
    for (int j = totO_s + tid; j < NO; j += 256) idxO_s[j] = 0;
    for (int j = totH_s + tid; j < NH; j += 256) idxH_s[j] = 0;
    __syncthreads();

    const float L0 = lat[0], L1 = lat[1], L2 = lat[2];

    // ---- gather + wrap: w = (x/L - floor(x/L)) * L ----
    const float* base = radii + ((size_t)t * R + r) * (size_t)N * 3;
    for (int i = tid; i < NO; i += 256) {
        const int g = idxO_s[i];
        float f0 = base[3 * g    ] / L0;
        float f1 = base[3 * g + 1] / L1;
        float f2 = base[3 * g + 2] / L2;
        sO[i] = make_float4((f0 - floorf(f0)) * L0, (f1 - floorf(f1)) * L1,
                            (f2 - floorf(f2)) * L2, 0.0f);
    }
    for (int i = tid; i < NH; i += 256) {
        const int g = idxH_s[i];
        float f0 = base[3 * g    ] / L0;
        float f1 = base[3 * g + 1] / L1;
        float f2 = base[3 * g + 2] / L2;
        sH[i] = make_float4((f0 - floorf(f0)) * L0, (f1 - floorf(f1)) * L1,
                            (f2 - floorf(f2)) * L2, 0.0f);
    }
    __syncthreads();

    const float b0 = bins_s[0], bN = bins_s[nb];
    const float inv_dx = (float)nb / (bN - b0);
    const float kc = -b0 * inv_dx;
    const int nbm1 = nb - 1;
    const unsigned hbase = (unsigned)__cvta_generic_to_shared(hist);

    // Symmetric types (OO, HH): each unordered pair once, weight 2
    // (weight 1 at the half-offset) -> counts identical to the full matrix.
    if (p < 2) {
        const float4* arr = (p == 0) ? sO : sH;
        const int n    = (p == 0) ? NO : NH;
        const int step = 256 / n;
        const int j    = tid & (n - 1);
        const int c0   = tid / n;
        const int half = n >> 1;
        const float4 B = arr[j];
        #pragma unroll 4
        for (int o = 1 + c0; o <= half; o += step) {
            const int i = (j + o) & (n - 1);
            const int w = (o == half) ? 1 : 2;
            do_pair(arr[i], B, L0, L1, L2, b0, bN, inv_dx, kc, nbm1,
                    bins_s, hbase, w);
        }
    } else {
        const int j  = tid & (NO - 1);
        const int c0 = tid >> 6;
        const float4 B = sO[j];
        #pragma unroll 4
        for (int i = c0; i < NH; i += 4) {
            do_pair(sH[i], B, L0, L1, L2, b0, bN, inv_dx, kc, nbm1,
                    bins_s, hbase, 1);
        }
    }
    __syncthreads();

    // ---- write hist + frame weight u = sum_b h[b]/shell[b] ----
    const float c43pi = (float)(4.0 / 3.0 * M_PI);
    float* gh = g_hists + ((size_t)rp * T + t) * nb;
    float acc = 0.0f;
    for (int i = tid; i < nb; i += 256) {
        const float h = (float)hist[i];
        gh[i] = h;
        const float lo = bins_s[i], hi = bins_s[i + 1];
        acc += __fdividef(h, c43pi * (hi * hi * hi - lo * lo * lo));
    }
    __syncthreads();                       // done reading hist as ints
    float* red = (float*)hist;             // reuse smem as reduce scratch
    red[tid] = acc;
    __syncthreads();
    #pragma unroll
    for (int s = 128; s > 0; s >>= 1) {
        if (tid < s) red[tid] += red[tid + s];
        __syncthreads();
    }
    if (tid == 0) g_u[rp * T + t] = red[0];
}

// ---------------------------------------------------------------------------
// rdf + MAE, chunked over bins: blockIdx.x = rp * NCH + c, chunk = 100 bins.
// rdf[b] = (S/T) * sum_t h[t,b] * inv_shell[b] / u_t,
// S = (vol/(T*P)) * sum_t u_t. Last block finalizes MAEs deterministically.
// ---------------------------------------------------------------------------
__global__ __launch_bounds__(128) void rdf_kernel(
    const float* __restrict__ bins,
    const float* __restrict__ lat,
    const float* __restrict__ gt_oo,
    const float* __restrict__ gt_hh,
    const float* __restrict__ gt_ho,
    float* __restrict__ out,
    int T, int nb, int R)
{
    __shared__ float invU[128];
    __shared__ float red[128];
    __shared__ int sdone;

    const int rp = blockIdx.x / NCH;
    const int c  = blockIdx.x % NCH;
    const int p = rp % 3;
    const int r = rp / 3;
    const int tid = threadIdx.x;
    const int chunk = (nb + NCH - 1) / NCH;          // 100

    // sumU + invU from g_u (tiny, L2-hot)
    float uv = (tid < T) ? g_u[rp * T + tid] : 0.0f;
    red[tid] = uv;
    __syncthreads();
    #pragma unroll
    for (int s = 64; s > 0; s >>= 1) {
        if (tid < s) red[tid] += red[tid + s];
        __syncthreads();
    }
    const float sumU = red[0];
    __syncthreads();
    invU[tid] = (tid < T) ? (1.0f / uv) : 0.0f;
    __syncthreads();

    const float vol = lat[0] * lat[1] * lat[2];
    const int P = (p == 0) ? NO * NO : (p == 1) ? NH * NH : NH * NO;
    const float SinvT = vol / ((float)T * (float)P) * sumU / (float)T;
    const float* gt = (p == 0) ? gt_oo : (p == 1) ? gt_hh : gt_ho;
    const float* H = g_hists + (size_t)rp * T * nb;

    const int b = c * chunk + tid;
    float myabs = 0.0f;
    if (tid < chunk && b < nb) {
        float num = 0.0f;
        #pragma unroll 4
        for (int t = 0; t < T; t++)
            num = fmaf(H[(size_t)t * nb + b], invU[t], num);
        const float c43pi = (float)(4.0 / 3.0 * M_PI);
        const float lo = bins[b], hi = bins[b + 1];
        const float rdf = SinvT * num / (c43pi * (hi * hi * hi - lo * lo * lo));
        out[((size_t)r * 3 + p) * nb + b] = rdf;
        myabs = fabsf(rdf - gt[b]);
    }
    red[tid] = myabs;
    __syncthreads();
    #pragma unroll
    for (int s = 64; s > 0; s >>= 1) {
        if (tid < s) red[tid] += red[tid + s];
        __syncthreads();
    }
    if (tid == 0) {
        g_mae_part[rp * NCH + c] = red[0];
        __threadfence();
        unsigned old = atomicAdd(&g_cnt, 1u);
        sdone = (int)(old == (unsigned)(3 * R * NCH - 1));
    }
    __syncthreads();
    if (sdone) {
        __threadfence();
        if (tid == 0) g_cnt = 0;                  // reset for next graph replay
        if (tid < R) {
            float m = -1.0f;
            #pragma unroll
            for (int pp = 0; pp < 3; pp++) {
                float s = 0.0f;
                for (int cc = 0; cc < NCH; cc++)   // fixed order: deterministic
                    s += g_mae_part[(tid * 3 + pp) * NCH + cc];
                m = fmaxf(m, 6.0f * s / (float)nb);
            }
            out[(size_t)R * 3 * nb + tid] = m;
        }
    }
}

// ---------------------------------------------------------------------------
extern "C" void kernel_launch(void* const* d_in, const int* in_sizes, int n_in,
                              void* d_out, int out_size) {
    const float* radii  = (const float*)d_in[0];   // (T,R,N,3)
    const int*   ptypes = (const int*)d_in[1];     // (N,)
    const float* lat    = (const float*)d_in[2];   // (3,)
    const float* bins   = (const float*)d_in[3];   // (nb+1,)
    const float* gt_oo  = (const float*)d_in[4];
    const float* gt_hh  = (const float*)d_in[5];
    const float* gt_ho  = (const float*)d_in[6];
    float* out = (float*)d_out;

    const int nb = in_sizes[3] - 1;                 // 600
    const int N  = in_sizes[1];                     // 192
    const int R  = out_size / (3 * nb + 1);         // 8
    const int T  = in_sizes[0] / (R * N * 3);       // 100

    hist_kernel<<<R * 3 * T, 256>>>(radii, ptypes, lat, bins, T, R, N, nb);
    rdf_kernel<<<R * 3 * NCH, 128>>>(bins, lat, gt_oo, gt_hh, gt_ho, out, T, nb, R);
}

// round 8
// speedup vs baseline: 1.9899x; 1.1641x over previous
#include <cuda_runtime.h>
#include <cuda_bf16.h>
#include <math.h>

#define NO 64
#define NH 128
#define NB_MAX 600
#define NCH 6            // bin chunks for the rdf kernel

// Scratch (allocation-free): per-frame hists R*3*T*nb = 1,440,000 floats.
__device__ float g_hists[1600000];
__device__ float g_u[4096];           // per-(rp,t) frame weights
__device__ float g_mae_part[32 * NCH];
__device__ unsigned g_cnt;            // completion counter (reset by last block)

// ---------------------------------------------------------------------------
// Branchless pair visit: min-image distance -> bin -> predicated shared red.
// ---------------------------------------------------------------------------
__device__ __forceinline__ void do_pair(
    const float4 A, const float4 B,
    const float L0, const float L1, const float L2,
    const float b0, const float bN, const float inv_dx, const float kc,
    const int nbm1, const float* __restrict__ bins_s,
    const unsigned hbase, const int w)
{
    float dx = fabsf(A.x - B.x); dx = fminf(dx, L0 - dx);
    float dy = fabsf(A.y - B.y); dy = fminf(dy, L1 - dy);
    float dz = fabsf(A.z - B.z); dz = fminf(dz, L2 - dz);
    const float s = fmaf(dx, dx, fmaf(dy, dy, dz * dz));

    // d = sqrt(s) via rsqrt.approx + one Newton step (~1 ulp).
    // s == 0 (self pair) -> inf -> NaN -> both range predicates false.
    float y; asm("rsqrt.approx.f32 %0, %1;" : "=f"(y) : "f"(s));
    const float x = s * y;
    const float d = x * fmaf(-0.5f * x, y, 1.5f);

    int k = (int)fmaf(d, inv_dx, kc);
    k = min(max(k, 0), nbm1);
    const float lo = bins_s[k];
    const float hi = bins_s[k + 1];
    k += (int)((hi <= d) & (k < nbm1));       // exact searchsorted fixup
    k -= (int)((lo >  d) & (k > 0));          // (mutually exclusive, branchless)

    const int ok = (int)((d >= b0) & (d <= bN));
    const unsigned addr = hbase + ((unsigned)k << 2);
    asm volatile(
        "{\n\t.reg .pred p;\n\t"
        "setp.ne.s32 p, %0, 0;\n\t"
        "@p red.shared.add.u32 [%1], %2;\n\t}"
        :: "r"(ok), "r"(addr), "r"(w) : "memory");
}

// ---------------------------------------------------------------------------
// One block per (replica, frame): ALL THREE pair-type histograms + weights.
// blockIdx.x = r*T + t. Coordinates gathered/wrapped once; 3 smem hists.
// ---------------------------------------------------------------------------
__global__ __launch_bounds__(256) void hist_kernel(
    const float* __restrict__ radii,   // (T, R, N, 3)
    const int*   __restrict__ ptypes,  // (N,)
    const float* __restrict__ lat,     // (3,)
    const float* __restrict__ bins,    // (nb+1,)
    int T, int R, int N, int nb)
{
    __shared__ int idxO_s[NO];
    __shared__ int idxH_s[NH];
    __shared__ float4 sO[NO];
    __shared__ float4 sH[NH];
    __shared__ float bins_s[NB_MAX + 1];
    __shared__ int hOO[NB_MAX];
    __shared__ int hHH[NB_MAX];
    __shared__ int hHO[NB_MAX];
    __shared__ int cO[8], cH[8], oO[8], oH[8];
    __shared__ int totO_s, totH_s;
    __shared__ float usum[8][3];

    const int bid = blockIdx.x;
    const int t = bid % T;
    const int r = bid / T;
    const int tid = threadIdx.x;
    const int wid = tid >> 5, lane = tid & 31;

    // ---- ballot-compaction of O/H index lists (N <= 256) ----
    const int ty = (tid < N) ? ptypes[tid] : -1;
    const unsigned mO = __ballot_sync(0xffffffffu, ty == 8);
    const unsigned mH = __ballot_sync(0xffffffffu, ty == 1);
    if (lane == 0) { cO[wid] = __popc(mO); cH[wid] = __popc(mH); }
    for (int i = tid; i <= nb; i += 256) bins_s[i] = bins[i];
    for (int i = tid; i < nb; i += 256) { hOO[i] = 0; hHH[i] = 0; hHO[i] = 0; }
    __syncthreads();
    if (tid == 0) {
        int aO = 0, aH = 0;
        #pragma unroll
        for (int w = 0; w < 8; w++) {
            oO[w] = aO; aO += cO[w];
            oH[w] = aH; aH += cH[w];
        }
        totO_s = aO; totH_s = aH;
    }
    __syncthreads();
    const unsigned lt = (1u << lane) - 1u;
    if (ty == 8) { int pos = oO[wid] + __popc(mO & lt); if (pos < NO) idxO_s[pos] = tid; }
    if (ty == 1) { int pos = oH[wid] + __popc(mH & lt); if (pos < NH) idxH_s[pos] = tid; }
    for (int j = totO_s + tid; j < NO; j += 256) idxO_s[j] = 0;
    for (int j = totH_s + tid; j < NH; j += 256) idxH_s[j] = 0;
    __syncthreads();

    const float L0 = lat[0], L1 = lat[1], L2 = lat[2];

    // ---- gather + wrap once: w = (x/L - floor(x/L)) * L ----
    const float* base = radii + ((size_t)t * R + r) * (size_t)N * 3;
    for (int i = tid; i < NO; i += 256) {
        const int g = idxO_s[i];
        float f0 = base[3 * g    ] / L0;
        float f1 = base[3 * g + 1] / L1;
        float f2 = base[3 * g + 2] / L2;
        sO[i] = make_float4((f0 - floorf(f0)) * L0, (f1 - floorf(f1)) * L1,
                            (f2 - floorf(f2)) * L2, 0.0f);
    }
    for (int i = tid; i < NH; i += 256) {
        const int g = idxH_s[i];
        float f0 = base[3 * g    ] / L0;
        float f1 = base[3 * g + 1] / L1;
        float f2 = base[3 * g + 2] / L2;
        sH[i] = make_float4((f0 - floorf(f0)) * L0, (f1 - floorf(f1)) * L1,
                            (f2 - floorf(f2)) * L2, 0.0f);
    }
    __syncthreads();

    const float b0 = bins_s[0], bN = bins_s[nb];
    const float inv_dx = (float)nb / (bN - b0);
    const float kc = -b0 * inv_dx;
    const int nbm1 = nb - 1;
    const unsigned hbOO = (unsigned)__cvta_generic_to_shared(hOO);
    const unsigned hbHH = (unsigned)__cvta_generic_to_shared(hHH);
    const unsigned hbHO = (unsigned)__cvta_generic_to_shared(hHO);

    // ---- phase 1: OO (symmetric, n=64; each unordered pair once, w=2;
    //      w=1 at the half-offset -> counts == full double-counted matrix) ----
    {
        const int j  = tid & (NO - 1);
        const int c0 = tid >> 6;                    // 0..3, step 4
        const float4 B = sO[j];
        #pragma unroll
        for (int o = 1 + c0; o <= 32; o += 4) {
            const int i = (j + o) & (NO - 1);
            const int w = (o == 32) ? 1 : 2;
            do_pair(sO[i], B, L0, L1, L2, b0, bN, inv_dx, kc, nbm1,
                    bins_s, hbOO, w);
        }
    }
    // ---- phase 2: HH (symmetric, n=128) ----
    {
        const int j  = tid & (NH - 1);
        const int c0 = tid >> 7;                    // 0..1, step 2
        const float4 B = sH[j];
        #pragma unroll 4
        for (int o = 1 + c0; o <= 64; o += 2) {
            const int i = (j + o) & (NH - 1);
            const int w = (o == 64) ? 1 : 2;
            do_pair(sH[i], B, L0, L1, L2, b0, bN, inv_dx, kc, nbm1,
                    bins_s, hbHH, w);
        }
    }
    // ---- phase 3: HO (all 128x64, w=1) ----
    {
        const int j  = tid & (NO - 1);
        const int c0 = tid >> 6;                    // 0..3
        const float4 B = sO[j];
        #pragma unroll 4
        for (int i = c0; i < NH; i += 4) {
            do_pair(sH[i], B, L0, L1, L2, b0, bN, inv_dx, kc, nbm1,
                    bins_s, hbHO, 1);
        }
    }
    __syncthreads();

    // ---- write 3 hists + frame weights u = sum_b h[b]/shell[b] ----
    const float c43pi = (float)(4.0 / 3.0 * M_PI);
    float* gh0 = g_hists + ((size_t)(r * 3 + 0) * T + t) * nb;
    float* gh1 = g_hists + ((size_t)(r * 3 + 1) * T + t) * nb;
    float* gh2 = g_hists + ((size_t)(r * 3 + 2) * T + t) * nb;
    float a0 = 0.0f, a1 = 0.0f, a2 = 0.0f;
    for (int i = tid; i < nb; i += 256) {
        const float lo = bins_s[i], hi = bins_s[i + 1];
        const float inv = __fdividef(1.0f, c43pi * (hi * hi * hi - lo * lo * lo));
        const float h0 = (float)hOO[i];
        const float h1 = (float)hHH[i];
        const float h2 = (float)hHO[i];
        gh0[i] = h0; gh1[i] = h1; gh2[i] = h2;
        a0 = fmaf(h0, inv, a0);
        a1 = fmaf(h1, inv, a1);
        a2 = fmaf(h2, inv, a2);
    }
    #pragma unroll
    for (int o = 16; o > 0; o >>= 1) {
        a0 += __shfl_xor_sync(0xffffffffu, a0, o);
        a1 += __shfl_xor_sync(0xffffffffu, a1, o);
        a2 += __shfl_xor_sync(0xffffffffu, a2, o);
    }
    if (lane == 0) { usum[wid][0] = a0; usum[wid][1] = a1; usum[wid][2] = a2; }
    __syncthreads();
    if (tid == 0) {
        float s0 = 0.0f, s1 = 0.0f, s2 = 0.0f;
        #pragma unroll
        for (int w = 0; w < 8; w++) {
            s0 += usum[w][0]; s1 += usum[w][1]; s2 += usum[w][2];
        }
        g_u[(r * 3 + 0) * T + t] = s0;
        g_u[(r * 3 + 1) * T + t] = s1;
        g_u[(r * 3 + 2) * T + t] = s2;
    }
}

// ---------------------------------------------------------------------------
// rdf + MAE, chunked over bins: blockIdx.x = rp * NCH + c, chunk = 100 bins.
// rdf[b] = (S/T) * sum_t h[t,b] * inv_shell[b] / u_t,
// S = (vol/(T*P)) * sum_t u_t. Last block finalizes MAEs deterministically.
// ---------------------------------------------------------------------------
__global__ __launch_bounds__(128) void rdf_kernel(
    const float* __restrict__ bins,
    const float* __restrict__ lat,
    const float* __restrict__ gt_oo,
    const float* __restrict__ gt_hh,
    const float* __restrict__ gt_ho,
    float* __restrict__ out,
    int T, int nb, int R)
{
    __shared__ float invU[128];
    __shared__ float red[128];
    __shared__ int sdone;

    const int rp = blockIdx.x / NCH;
    const int c  = blockIdx.x % NCH;
    const int p = rp % 3;
    const int r = rp / 3;
    const int tid = threadIdx.x;
    const int chunk = (nb + NCH - 1) / NCH;          // 100

    // sumU + invU from g_u (tiny, L2-hot)
    float uv = (tid < T) ? g_u[rp * T + tid] : 0.0f;
    red[tid] = uv;
    __syncthreads();
    #pragma unroll
    for (int s = 64; s > 0; s >>= 1) {
        if (tid < s) red[tid] += red[tid + s];
        __syncthreads();
    }
    const float sumU = red[0];
    __syncthreads();
    invU[tid] = (tid < T) ? (1.0f / uv) : 0.0f;
    __syncthreads();

    const float vol = lat[0] * lat[1] * lat[2];
    const int P = (p == 0) ? NO * NO : (p == 1) ? NH * NH : NH * NO;
    const float SinvT = vol / ((float)T * (float)P) * sumU / (float)T;
    const float* gt = (p == 0) ? gt_oo : (p == 1) ? gt_hh : gt_ho;
    const float* H = g_hists + (size_t)rp * T * nb;

    const int b = c * chunk + tid;
    float myabs = 0.0f;
    if (tid < chunk && b < nb) {
        float num = 0.0f;
        #pragma unroll 8
        for (int t = 0; t < T; t++)
            num = fmaf(H[(size_t)t * nb + b], invU[t], num);
        const float c43pi = (float)(4.0 / 3.0 * M_PI);
        const float lo = bins[b], hi = bins[b + 1];
        const float rdf = SinvT * num / (c43pi * (hi * hi * hi - lo * lo * lo));
        out[((size_t)r * 3 + p) * nb + b] = rdf;
        myabs = fabsf(rdf - gt[b]);
    }
    red[tid] = myabs;
    __syncthreads();
    #pragma unroll
    for (int s = 64; s > 0; s >>= 1) {
        if (tid < s) red[tid] += red[tid + s];
        __syncthreads();
    }
    if (tid == 0) {
        g_mae_part[rp * NCH + c] = red[0];
        __threadfence();
        unsigned old = atomicAdd(&g_cnt, 1u);
        sdone = (int)(old == (unsigned)(3 * R * NCH - 1));
    }
    __syncthreads();
    if (sdone) {
        __threadfence();
        if (tid == 0) g_cnt = 0;                  // reset for next graph replay
        if (tid < R) {
            float m = -1.0f;
            #pragma unroll
            for (int pp = 0; pp < 3; pp++) {
                float s = 0.0f;
                for (int cc = 0; cc < NCH; cc++)   // fixed order: deterministic
                    s += g_mae_part[(tid * 3 + pp) * NCH + cc];
                m = fmaxf(m, 6.0f * s / (float)nb);
            }
            out[(size_t)R * 3 * nb + tid] = m;
        }
    }
}

// ---------------------------------------------------------------------------
extern "C" void kernel_launch(void* const* d_in, const int* in_sizes, int n_in,
                              void* d_out, int out_size) {
    const float* radii  = (const float*)d_in[0];   // (T,R,N,3)
    const int*   ptypes = (const int*)d_in[1];     // (N,)
    const float* lat    = (const float*)d_in[2];   // (3,)
    const float* bins   = (const float*)d_in[3];   // (nb+1,)
    const float* gt_oo  = (const float*)d_in[4];
    const float* gt_hh  = (const float*)d_in[5];
    const float* gt_ho  = (const float*)d_in[6];
    float* out = (float*)d_out;

    const int nb = in_sizes[3] - 1;                 // 600
    const int N  = in_sizes[1];                     // 192
    const int R  = out_size / (3 * nb + 1);         // 8
    const int T  = in_sizes[0] / (R * N * 3);       // 100

    hist_kernel<<<R * T, 256>>>(radii, ptypes, lat, bins, T, R, N, nb);
    rdf_kernel<<<R * 3 * NCH, 128>>>(bins, lat, gt_oo, gt_hh, gt_ho, out, T, nb, R);
}

// round 9
// speedup vs baseline: 2.0102x; 1.0102x over previous
#include <cuda_runtime.h>
#include <cuda_bf16.h>
#include <math.h>

#define NO 64
#define NH 128
#define NB_MAX 600
#define NCH 6            // bin chunks for the rdf kernel

// Scratch (allocation-free): per-frame hists R*3*T*nb = 1,440,000 floats.
__device__ float g_hists[1600000];
__device__ float g_u[4096];           // per-(rp,t) frame weights
__device__ float g_mae_part[32 * NCH];
__device__ unsigned g_cnt;            // completion counter (reset by last block)

// ---------------------------------------------------------------------------
// Branchless pair visit: min-image distance -> bin -> predicated shared red.
// Edge fixup uses ONE LDS.64 from the (lo,hi) float2 table.
// ---------------------------------------------------------------------------
__device__ __forceinline__ void do_pair(
    const float4 A, const float4 B,
    const float L0, const float L1, const float L2,
    const float b0, const float bN, const float inv_dx, const float kc,
    const int nbm1, const float2* __restrict__ e2_s,
    const unsigned hbase, const int w)
{
    float dx = fabsf(A.x - B.x); dx = fminf(dx, L0 - dx);
    float dy = fabsf(A.y - B.y); dy = fminf(dy, L1 - dy);
    float dz = fabsf(A.z - B.z); dz = fminf(dz, L2 - dz);
    const float s = fmaf(dx, dx, fmaf(dy, dy, dz * dz));

    // d = sqrt(s) via rsqrt.approx + one Newton step (~1 ulp).
    // s == 0 (self pair) -> inf -> NaN -> both range predicates false.
    float y; asm("rsqrt.approx.f32 %0, %1;" : "=f"(y) : "f"(s));
    const float x = s * y;
    const float d = x * fmaf(-0.5f * x, y, 1.5f);

    int k = (int)fmaf(d, inv_dx, kc);
    k = min(max(k, 0), nbm1);
    const float2 e = e2_s[k];                 // (bins[k], bins[k+1]) in one LDS.64
    k += (int)((e.y <= d) & (k < nbm1));      // exact searchsorted fixup
    k -= (int)((e.x >  d) & (k > 0));         // (mutually exclusive, branchless)

    const int ok = (int)((d >= b0) & (d <= bN));
    const unsigned addr = hbase + ((unsigned)k << 2);
    asm volatile(
        "{\n\t.reg .pred p;\n\t"
        "setp.ne.s32 p, %0, 0;\n\t"
        "@p red.shared.add.u32 [%1], %2;\n\t}"
        :: "r"(ok), "r"(addr), "r"(w) : "memory");
}

// ---------------------------------------------------------------------------
// One block per (replica, frame): ALL THREE pair-type histograms + weights.
// blockIdx.x = r*T + t. Coordinates gathered/wrapped once; 3 smem hists.
// ---------------------------------------------------------------------------
__global__ __launch_bounds__(256) void hist_kernel(
    const float* __restrict__ radii,   // (T, R, N, 3)
    const int*   __restrict__ ptypes,  // (N,)
    const float* __restrict__ lat,     // (3,)
    const float* __restrict__ bins,    // (nb+1,)
    int T, int R, int N, int nb)
{
    __shared__ int idxO_s[NO];
    __shared__ int idxH_s[NH];
    __shared__ float4 sO[NO];
    __shared__ float4 sH[NH];
    __shared__ float2 e2_s[NB_MAX];    // (bins[k], bins[k+1]) pairs
    __shared__ int hOO[NB_MAX];
    __shared__ int hHH[NB_MAX];
    __shared__ int hHO[NB_MAX];
    __shared__ int cO[8], cH[8], oO[8], oH[8];
    __shared__ int totO_s, totH_s;
    __shared__ float usum[8][3];

    const int bid = blockIdx.x;
    const int t = bid % T;
    const int r = bid / T;
    const int tid = threadIdx.x;
    const int wid = tid >> 5, lane = tid & 31;

    // ---- ballot-compaction of O/H index lists (N <= 256) ----
    const int ty = (tid < N) ? ptypes[tid] : -1;
    const unsigned mO = __ballot_sync(0xffffffffu, ty == 8);
    const unsigned mH = __ballot_sync(0xffffffffu, ty == 1);
    if (lane == 0) { cO[wid] = __popc(mO); cH[wid] = __popc(mH); }
    for (int i = tid; i < nb; i += 256) {
        e2_s[i] = make_float2(bins[i], bins[i + 1]);
        hOO[i] = 0; hHH[i] = 0; hHO[i] = 0;
    }
    __syncthreads();
    if (tid == 0) {
        int aO = 0, aH = 0;
        #pragma unroll
        for (int w = 0; w < 8; w++) {
            oO[w] = aO; aO += cO[w];
            oH[w] = aH; aH += cH[w];
        }
        totO_s = aO; totH_s = aH;
    }
    __syncthreads();
    const unsigned lt = (1u << lane) - 1u;
    if (ty == 8) { int pos = oO[wid] + __popc(mO & lt); if (pos < NO) idxO_s[pos] = tid; }
    if (ty == 1) { int pos = oH[wid] + __popc(mH & lt); if (pos < NH) idxH_s[pos] = tid; }
    for (int j = totO_s + tid; j < NO; j += 256) idxO_s[j] = 0;
    for (int j = totH_s + tid; j < NH; j += 256) idxH_s[j] = 0;
    __syncthreads();

    const float L0 = lat[0], L1 = lat[1], L2 = lat[2];
    const float rL0 = 1.0f / L0, rL1 = 1.0f / L1, rL2 = 1.0f / L2;

    // ---- gather + wrap once: w = frac(x/L)*L.  (reciprocal-multiply: a
    //      floor flip near a multiple of L shifts the coord by ~L, which is
    //      invariant under the min-image distance -> safe) ----
    const float* base = radii + ((size_t)t * R + r) * (size_t)N * 3;
    for (int i = tid; i < NO; i += 256) {
        const int g = idxO_s[i];
        float f0 = base[3 * g    ] * rL0;
        float f1 = base[3 * g + 1] * rL1;
        float f2 = base[3 * g + 2] * rL2;
        sO[i] = make_float4((f0 - floorf(f0)) * L0, (f1 - floorf(f1)) * L1,
                            (f2 - floorf(f2)) * L2, 0.0f);
    }
    for (int i = tid; i < NH; i += 256) {
        const int g = idxH_s[i];
        float f0 = base[3 * g    ] * rL0;
        float f1 = base[3 * g + 1] * rL1;
        float f2 = base[3 * g + 2] * rL2;
        sH[i] = make_float4((f0 - floorf(f0)) * L0, (f1 - floorf(f1)) * L1,
                            (f2 - floorf(f2)) * L2, 0.0f);
    }
    __syncthreads();

    const float b0 = e2_s[0].x, bN = e2_s[nb - 1].y;
    const float inv_dx = (float)nb / (bN - b0);
    const float kc = -b0 * inv_dx;
    const int nbm1 = nb - 1;
    const unsigned hbOO = (unsigned)__cvta_generic_to_shared(hOO);
    const unsigned hbHH = (unsigned)__cvta_generic_to_shared(hHH);
    const unsigned hbHO = (unsigned)__cvta_generic_to_shared(hHO);

    // ---- phase 1: OO (symmetric, n=64; each unordered pair once, w=2;
    //      w=1 at the half-offset -> counts == full double-counted matrix) ----
    {
        const int j  = tid & (NO - 1);
        const int c0 = tid >> 6;                    // 0..3, step 4
        const float4 B = sO[j];
        #pragma unroll
        for (int o = 1 + c0; o <= 32; o += 4) {
            const int i = (j + o) & (NO - 1);
            const int w = (o == 32) ? 1 : 2;
            do_pair(sO[i], B, L0, L1, L2, b0, bN, inv_dx, kc, nbm1,
                    e2_s, hbOO, w);
        }
    }
    // ---- phase 2: HH (symmetric, n=128) ----
    {
        const int j  = tid & (NH - 1);
        const int c0 = tid >> 7;                    // 0..1, step 2
        const float4 B = sH[j];
        #pragma unroll 8
        for (int o = 1 + c0; o <= 64; o += 2) {
            const int i = (j + o) & (NH - 1);
            const int w = (o == 64) ? 1 : 2;
            do_pair(sH[i], B, L0, L1, L2, b0, bN, inv_dx, kc, nbm1,
                    e2_s, hbHH, w);
        }
    }
    // ---- phase 3: HO (all 128x64, w=1) ----
    {
        const int j  = tid & (NO - 1);
        const int c0 = tid >> 6;                    // 0..3
        const float4 B = sO[j];
        #pragma unroll 8
        for (int i = c0; i < NH; i += 4) {
            do_pair(sH[i], B, L0, L1, L2, b0, bN, inv_dx, kc, nbm1,
                    e2_s, hbHO, 1);
        }
    }
    __syncthreads();

    // ---- write 3 hists + frame weights u = sum_b h[b]/shell[b] ----
    const float c43pi = (float)(4.0 / 3.0 * M_PI);
    float* gh0 = g_hists + ((size_t)(r * 3 + 0) * T + t) * nb;
    float* gh1 = g_hists + ((size_t)(r * 3 + 1) * T + t) * nb;
    float* gh2 = g_hists + ((size_t)(r * 3 + 2) * T + t) * nb;
    float a0 = 0.0f, a1 = 0.0f, a2 = 0.0f;
    for (int i = tid; i < nb; i += 256) {
        const float2 e = e2_s[i];
        const float inv = __fdividef(1.0f, c43pi * (e.y * e.y * e.y - e.x * e.x * e.x));
        const float h0 = (float)hOO[i];
        const float h1 = (float)hHH[i];
        const float h2 = (float)hHO[i];
        gh0[i] = h0; gh1[i] = h1; gh2[i] = h2;
        a0 = fmaf(h0, inv, a0);
        a1 = fmaf(h1, inv, a1);
        a2 = fmaf(h2, inv, a2);
    }
    #pragma unroll
    for (int o = 16; o > 0; o >>= 1) {
        a0 += __shfl_xor_sync(0xffffffffu, a0, o);
        a1 += __shfl_xor_sync(0xffffffffu, a1, o);
        a2 += __shfl_xor_sync(0xffffffffu, a2, o);
    }
    if (lane == 0) { usum[wid][0] = a0; usum[wid][1] = a1; usum[wid][2] = a2; }
    __syncthreads();
    if (tid == 0) {
        float s0 = 0.0f, s1 = 0.0f, s2 = 0.0f;
        #pragma unroll
        for (int w = 0; w < 8; w++) {
            s0 += usum[w][0]; s1 += usum[w][1]; s2 += usum[w][2];
        }
        g_u[(r * 3 + 0) * T + t] = s0;
        g_u[(r * 3 + 1) * T + t] = s1;
        g_u[(r * 3 + 2) * T + t] = s2;
    }
}

// ---------------------------------------------------------------------------
// rdf + MAE, chunked over bins: blockIdx.x = rp * NCH + c, chunk = 100 bins.
// rdf[b] = (S/T) * sum_t h[t,b] * inv_shell[b] / u_t,
// S = (vol/(T*P)) * sum_t u_t. Last block finalizes MAEs deterministically.
// ---------------------------------------------------------------------------
__global__ __launch_bounds__(128) void rdf_kernel(
    const float* __restrict__ bins,
    const float* __restrict__ lat,
    const float* __restrict__ gt_oo,
    const float* __restrict__ gt_hh,
    const float* __restrict__ gt_ho,
    float* __restrict__ out,
    int T, int nb, int R)
{
    __shared__ float invU[128];
    __shared__ float red[128];
    __shared__ int sdone;

    const int rp = blockIdx.x / NCH;
    const int c  = blockIdx.x % NCH;
    const int p = rp % 3;
    const int r = rp / 3;
    const int tid = threadIdx.x;
    const int chunk = (nb + NCH - 1) / NCH;          // 100

    // sumU + invU from g_u (tiny, L2-hot)
    float uv = (tid < T) ? g_u[rp * T + tid] : 0.0f;
    red[tid] = uv;
    __syncthreads();
    #pragma unroll
    for (int s = 64; s > 0; s >>= 1) {
        if (tid < s) red[tid] += red[tid + s];
        __syncthreads();
    }
    const float sumU = red[0];
    __syncthreads();
    invU[tid] = (tid < T) ? (1.0f / uv) : 0.0f;
    __syncthreads();

    const float vol = lat[0] * lat[1] * lat[2];
    const int P = (p == 0) ? NO * NO : (p == 1) ? NH * NH : NH * NO;
    const float SinvT = vol / ((float)T * (float)P) * sumU / (float)T;
    const float* gt = (p == 0) ? gt_oo : (p == 1) ? gt_hh : gt_ho;
    const float* H = g_hists + (size_t)rp * T * nb;

    const int b = c * chunk + tid;
    float myabs = 0.0f;
    if (tid < chunk && b < nb) {
        float num = 0.0f;
        #pragma unroll 8
        for (int t = 0; t < T; t++)
            num = fmaf(H[(size_t)t * nb + b], invU[t], num);
        const float c43pi = (float)(4.0 / 3.0 * M_PI);
        const float lo = bins[b], hi = bins[b + 1];
        const float rdf = SinvT * num / (c43pi * (hi * hi * hi - lo * lo * lo));
        out[((size_t)r * 3 + p) * nb + b] = rdf;
        myabs = fabsf(rdf - gt[b]);
    }
    red[tid] = myabs;
    __syncthreads();
    #pragma unroll
    for (int s = 64; s > 0; s >>= 1) {
        if (tid < s) red[tid] += red[tid + s];
        __syncthreads();
    }
    if (tid == 0) {
        g_mae_part[rp * NCH + c] = red[0];
        __threadfence();
        unsigned old = atomicAdd(&g_cnt, 1u);
        sdone = (int)(old == (unsigned)(3 * R * NCH - 1));
    }
    __syncthreads();
    if (sdone) {
        __threadfence();
        if (tid == 0) g_cnt = 0;                  // reset for next graph replay
        if (tid < R) {
            float m = -1.0f;
            #pragma unroll
            for (int pp = 0; pp < 3; pp++) {
                float s = 0.0f;
                for (int cc = 0; cc < NCH; cc++)   // fixed order: deterministic
                    s += g_mae_part[(tid * 3 + pp) * NCH + cc];
                m = fmaxf(m, 6.0f * s / (float)nb);
            }
            out[(size_t)R * 3 * nb + tid] = m;
        }
    }
}

// ---------------------------------------------------------------------------
extern "C" void kernel_launch(void* const* d_in, const int* in_sizes, int n_in,
                              void* d_out, int out_size) {
    const float* radii  = (const float*)d_in[0];   // (T,R,N,3)
    const int*   ptypes = (const int*)d_in[1];     // (N,)
    const float* lat    = (const float*)d_in[2];   // (3,)
    const float* bins   = (const float*)d_in[3];   // (nb+1,)
    const float* gt_oo  = (const float*)d_in[4];
    const float* gt_hh  = (const float*)d_in[5];
    const float* gt_ho  = (const float*)d_in[6];
    float* out = (float*)d_out;

    const int nb = in_sizes[3] - 1;                 // 600
    const int N  = in_sizes[1];                     // 192
    const int R  = out_size / (3 * nb + 1);         // 8
    const int T  = in_sizes[0] / (R * N * 3);       // 100

    hist_kernel<<<R * T, 256>>>(radii, ptypes, lat, bins, T, R, N, nb);
    rdf_kernel<<<R * 3 * NCH, 128>>>(bins, lat, gt_oo, gt_hh, gt_ho, out, T, nb, R);
}

// round 10
// speedup vs baseline: 2.7348x; 1.3604x over previous
#include <cuda_runtime.h>
#include <cuda_bf16.h>
#include <math.h>

#define NO 64
#define NH 128
#define NB_MAX 600

// Scratch (allocation-free; zero-initialized at module load, re-zeroed by
// rdf_kernel after each use so every graph replay starts clean).
__device__ float g_num[32 * 3 * NB_MAX];   // per-(rp,b) rdf numerators
__device__ float g_sumU[32 * 3];           // per-rp sum of frame weights
__device__ float g_maes[32 * 3];
__device__ unsigned g_cnt;                 // completion counter (reset by last block)

// ---------------------------------------------------------------------------
// Branchless pair visit: min-image distance -> analytic bin -> predicated
// shared red. (bins are linspace; analytic index == searchsorted except for
// d within ~1ulp of an edge -> ±1-bin shifts on ~1e-4 of pairs, ~1e-5 rel.)
// ---------------------------------------------------------------------------
__device__ __forceinline__ void do_pair(
    const float4 A, const float4 B,
    const float L0, const float L1, const float L2,
    const float b0, const float bN, const float inv_dx, const float kc,
    const int nbm1, const unsigned hbase, const int w)
{
    float dx = fabsf(A.x - B.x); dx = fminf(dx, L0 - dx);
    float dy = fabsf(A.y - B.y); dy = fminf(dy, L1 - dy);
    float dz = fabsf(A.z - B.z); dz = fminf(dz, L2 - dz);
    const float s = fmaf(dx, dx, fmaf(dy, dy, dz * dz));

    // d = sqrt(s) via rsqrt.approx + one Newton step (~1 ulp).
    // s == 0 (self pair) -> inf -> NaN -> both range predicates false.
    float y; asm("rsqrt.approx.f32 %0, %1;" : "=f"(y) : "f"(s));
    const float x = s * y;
    const float d = x * fmaf(-0.5f * x, y, 1.5f);

    int k = (int)fmaf(d, inv_dx, kc);
    k = min(max(k, 0), nbm1);

    const int ok = (int)((d >= b0) & (d <= bN));
    const unsigned addr = hbase + ((unsigned)k << 2);
    asm volatile(
        "{\n\t.reg .pred p;\n\t"
        "setp.ne.s32 p, %0, 0;\n\t"
        "@p red.shared.add.u32 [%1], %2;\n\t}"
        :: "r"(ok), "r"(addr), "r"(w) : "memory");
}

// ---------------------------------------------------------------------------
// One block per (replica, frame): ALL THREE pair-type histograms.
// blockIdx.x = r*T + t. Epilogue computes this frame's weight u per pair
// type and directly accumulates num[rp,b] += h[b]/u and sumU[rp] += u via
// global float RED — no per-frame histograms ever hit global memory.
// ---------------------------------------------------------------------------
__global__ __launch_bounds__(256) void hist_kernel(
    const float* __restrict__ radii,   // (T, R, N, 3)
    const int*   __restrict__ ptypes,  // (N,)
    const float* __restrict__ lat,     // (3,)
    const float* __restrict__ bins,    // (nb+1,)
    int T, int R, int N, int nb)
{
    __shared__ int idxO_s[NO];
    __shared__ int idxH_s[NH];
    __shared__ float4 sO[NO];
    __shared__ float4 sH[NH];
    __shared__ int hOO[NB_MAX];
    __shared__ int hHH[NB_MAX];
    __shared__ int hHO[NB_MAX];
    __shared__ int cO[8], cH[8], oO[8], oH[8];
    __shared__ int totO_s, totH_s;
    __shared__ float usum[8][3];
    __shared__ float ubc[3];

    const int bid = blockIdx.x;
    const int t = bid % T;
    const int r = bid / T;
    const int tid = threadIdx.x;
    const int wid = tid >> 5, lane = tid & 31;

    // ---- ballot-compaction of O/H index lists (N <= 256) ----
    const int ty = (tid < N) ? ptypes[tid] : -1;
    const unsigned mO = __ballot_sync(0xffffffffu, ty == 8);
    const unsigned mH = __ballot_sync(0xffffffffu, ty == 1);
    if (lane == 0) { cO[wid] = __popc(mO); cH[wid] = __popc(mH); }
    for (int i = tid; i < nb; i += 256) { hOO[i] = 0; hHH[i] = 0; hHO[i] = 0; }
    __syncthreads();
    if (tid == 0) {
        int aO = 0, aH = 0;
        #pragma unroll
        for (int w = 0; w < 8; w++) {
            oO[w] = aO; aO += cO[w];
            oH[w] = aH; aH += cH[w];
        }
        totO_s = aO; totH_s = aH;
    }
    __syncthreads();
    const unsigned lt = (1u << lane) - 1u;
    if (ty == 8) { int pos = oO[wid] + __popc(mO & lt); if (pos < NO) idxO_s[pos] = tid; }
    if (ty == 1) { int pos = oH[wid] + __popc(mH & lt); if (pos < NH) idxH_s[pos] = tid; }
    for (int j = totO_s + tid; j < NO; j += 256) idxO_s[j] = 0;
    for (int j = totH_s + tid; j < NH; j += 256) idxH_s[j] = 0;
    __syncthreads();

    const float L0 = lat[0], L1 = lat[1], L2 = lat[2];
    const float rL0 = 1.0f / L0, rL1 = 1.0f / L1, rL2 = 1.0f / L2;

    // ---- gather + wrap once: w = frac(x/L)*L (reciprocal-multiply: a floor
    //      flip shifts the coord by ~L, invariant under min-image) ----
    const float* base = radii + ((size_t)t * R + r) * (size_t)N * 3;
    for (int i = tid; i < NO; i += 256) {
        const int g = idxO_s[i];
        float f0 = base[3 * g    ] * rL0;
        float f1 = base[3 * g + 1] * rL1;
        float f2 = base[3 * g + 2] * rL2;
        sO[i] = make_float4((f0 - floorf(f0)) * L0, (f1 - floorf(f1)) * L1,
                            (f2 - floorf(f2)) * L2, 0.0f);
    }
    for (int i = tid; i < NH; i += 256) {
        const int g = idxH_s[i];
        float f0 = base[3 * g    ] * rL0;
        float f1 = base[3 * g + 1] * rL1;
        float f2 = base[3 * g + 2] * rL2;
        sH[i] = make_float4((f0 - floorf(f0)) * L0, (f1 - floorf(f1)) * L1,
                            (f2 - floorf(f2)) * L2, 0.0f);
    }
    __syncthreads();

    const float b0 = bins[0], bN = bins[nb];
    const float inv_dx = (float)nb / (bN - b0);
    const float kc = -b0 * inv_dx;
    const int nbm1 = nb - 1;
    const unsigned hbOO = (unsigned)__cvta_generic_to_shared(hOO);
    const unsigned hbHH = (unsigned)__cvta_generic_to_shared(hHH);
    const unsigned hbHO = (unsigned)__cvta_generic_to_shared(hHO);

    // ---- phase 1: OO (symmetric, n=64; each unordered pair once, w=2;
    //      w=1 at the half-offset -> counts == full double-counted matrix) ----
    {
        const int j  = tid & (NO - 1);
        const int c0 = tid >> 6;                    // 0..3, step 4
        const float4 B = sO[j];
        #pragma unroll
        for (int o = 1 + c0; o <= 32; o += 4) {
            const int i = (j + o) & (NO - 1);
            const int w = (o == 32) ? 1 : 2;
            do_pair(sO[i], B, L0, L1, L2, b0, bN, inv_dx, kc, nbm1, hbOO, w);
        }
    }
    // ---- phase 2: HH (symmetric, n=128) ----
    {
        const int j  = tid & (NH - 1);
        const int c0 = tid >> 7;                    // 0..1, step 2
        const float4 B = sH[j];
        #pragma unroll 8
        for (int o = 1 + c0; o <= 64; o += 2) {
            const int i = (j + o) & (NH - 1);
            const int w = (o == 64) ? 1 : 2;
            do_pair(sH[i], B, L0, L1, L2, b0, bN, inv_dx, kc, nbm1, hbHH, w);
        }
    }
    // ---- phase 3: HO (all 128x64, w=1) ----
    {
        const int j  = tid & (NO - 1);
        const int c0 = tid >> 6;                    // 0..3
        const float4 B = sO[j];
        #pragma unroll 8
        for (int i = c0; i < NH; i += 4) {
            do_pair(sH[i], B, L0, L1, L2, b0, bN, inv_dx, kc, nbm1, hbHO, 1);
        }
    }
    __syncthreads();

    // ---- epilogue: u = sum_b h[b]/shell[b] per pair type ----
    const float c43pi = (float)(4.0 / 3.0 * M_PI);
    float a0 = 0.0f, a1 = 0.0f, a2 = 0.0f;
    for (int i = tid; i < nb; i += 256) {
        const float lo = bins[i], hi = bins[i + 1];
        const float inv = __fdividef(1.0f, c43pi * (hi * hi * hi - lo * lo * lo));
        a0 = fmaf((float)hOO[i], inv, a0);
        a1 = fmaf((float)hHH[i], inv, a1);
        a2 = fmaf((float)hHO[i], inv, a2);
    }
    #pragma unroll
    for (int o = 16; o > 0; o >>= 1) {
        a0 += __shfl_xor_sync(0xffffffffu, a0, o);
        a1 += __shfl_xor_sync(0xffffffffu, a1, o);
        a2 += __shfl_xor_sync(0xffffffffu, a2, o);
    }
    if (lane == 0) { usum[wid][0] = a0; usum[wid][1] = a1; usum[wid][2] = a2; }
    __syncthreads();
    if (tid == 0) {
        float s0 = 0.0f, s1 = 0.0f, s2 = 0.0f;
        #pragma unroll
        for (int w = 0; w < 8; w++) {
            s0 += usum[w][0]; s1 += usum[w][1]; s2 += usum[w][2];
        }
        ubc[0] = s0; ubc[1] = s1; ubc[2] = s2;
        atomicAdd(&g_sumU[r * 3 + 0], s0);
        atomicAdd(&g_sumU[r * 3 + 1], s1);
        atomicAdd(&g_sumU[r * 3 + 2], s2);
    }
    __syncthreads();

    // ---- accumulate num[rp,b] += h[b]/u directly (kills g_hists) ----
    const float iu0 = 1.0f / ubc[0];
    const float iu1 = 1.0f / ubc[1];
    const float iu2 = 1.0f / ubc[2];
    float* n0 = g_num + (size_t)(r * 3 + 0) * NB_MAX;
    float* n1 = g_num + (size_t)(r * 3 + 1) * NB_MAX;
    float* n2 = g_num + (size_t)(r * 3 + 2) * NB_MAX;
    for (int i = tid; i < nb; i += 256) {
        const int h0 = hOO[i], h1 = hHH[i], h2 = hHO[i];
        if (h0) atomicAdd(&n0[i], (float)h0 * iu0);
        if (h1) atomicAdd(&n1[i], (float)h1 * iu1);
        if (h2) atomicAdd(&n2[i], (float)h2 * iu2);
    }
}

// ---------------------------------------------------------------------------
// rdf + MAE from accumulated numerators: blockIdx.x = rp (24 blocks).
// rdf[b] = (sumU * vol/(T*P)/T) * num[b] / shell[b]. Re-zeros its scratch
// for the next graph replay; last block finalizes the per-replica MAE max.
// ---------------------------------------------------------------------------
__global__ __launch_bounds__(256) void rdf_kernel(
    const float* __restrict__ bins,
    const float* __restrict__ lat,
    const float* __restrict__ gt_oo,
    const float* __restrict__ gt_hh,
    const float* __restrict__ gt_ho,
    float* __restrict__ out,
    int T, int nb, int R)
{
    __shared__ float red[256];
    __shared__ int sdone;

    const int rp = blockIdx.x;
    const int p = rp % 3;
    const int r = rp / 3;
    const int tid = threadIdx.x;

    const float vol = lat[0] * lat[1] * lat[2];
    const int P = (p == 0) ? NO * NO : (p == 1) ? NH * NH : NH * NO;
    const float sumU = g_sumU[rp];
    const float SinvT = vol / ((float)T * (float)P) * sumU / (float)T;
    const float* gt = (p == 0) ? gt_oo : (p == 1) ? gt_hh : gt_ho;
    const float* num = g_num + (size_t)rp * NB_MAX;
    const float c43pi = (float)(4.0 / 3.0 * M_PI);

    float* ro = out + ((size_t)r * 3 + p) * nb;
    float myabs = 0.0f;
    for (int b = tid; b < nb; b += 256) {
        const float lo = bins[b], hi = bins[b + 1];
        const float rdf = SinvT * num[b] / (c43pi * (hi * hi * hi - lo * lo * lo));
        ro[b] = rdf;
        myabs += fabsf(rdf - gt[b]);
    }
    red[tid] = myabs;
    __syncthreads();

    // re-zero scratch for the next replay (all reads of num/sumU are done)
    for (int b = tid; b < nb; b += 256) ((float*)num)[b] = 0.0f;
    if (tid == 0) g_sumU[rp] = 0.0f;

    #pragma unroll
    for (int s = 128; s > 0; s >>= 1) {
        if (tid < s) red[tid] += red[tid + s];
        __syncthreads();
    }
    if (tid == 0) {
        g_maes[rp] = 6.0f * red[0] / (float)nb;   // XLIM * mean
        __threadfence();
        unsigned old = atomicAdd(&g_cnt, 1u);
        sdone = (int)(old == (unsigned)(3 * R - 1));
    }
    __syncthreads();
    if (sdone) {
        __threadfence();
        if (tid == 0) g_cnt = 0;                  // reset for next graph replay
        if (tid < R) {
            volatile float* gm = g_maes;
            float m = gm[tid * 3];
            m = fmaxf(m, gm[tid * 3 + 1]);
            m = fmaxf(m, gm[tid * 3 + 2]);
            out[(size_t)R * 3 * nb + tid] = m;
        }
    }
}

// ---------------------------------------------------------------------------
extern "C" void kernel_launch(void* const* d_in, const int* in_sizes, int n_in,
                              void* d_out, int out_size) {
    const float* radii  = (const float*)d_in[0];   // (T,R,N,3)
    const int*   ptypes = (const int*)d_in[1];     // (N,)
    const float* lat    = (const float*)d_in[2];   // (3,)
    const float* bins   = (const float*)d_in[3];   // (nb+1,)
    const float* gt_oo  = (const float*)d_in[4];
    const float* gt_hh  = (const float*)d_in[5];
    const float* gt_ho  = (const float*)d_in[6];
    float* out = (float*)d_out;

    const int nb = in_sizes[3] - 1;                 // 600
    const int N  = in_sizes[1];                     // 192
    const int R  = out_size / (3 * nb + 1);         // 8
    const int T  = in_sizes[0] / (R * N * 3);       // 100

    hist_kernel<<<R * T, 256>>>(radii, ptypes, lat, bins, T, R, N, nb);
    rdf_kernel<<<R * 3, 256>>>(bins, lat, gt_oo, gt_hh, gt_ho, out, T, nb, R);
}